// round 16
// baseline (speedup 1.0000x reference)
#include <cuda_runtime.h>
#include <cuda_fp16.h>
#include <cstdint>
#include <cstddef>

// ---------------------------------------------------------------------------
// Problem constants
// ---------------------------------------------------------------------------
#define TT    512
#define BB    256
#define NIN   128      // NINP (127 input + 1 dt)
#define NH    512      // NHID
#define NGATE 2048     // 4*NHID
#define KTOT  640      // NIN + NH
#define NOUT  64

// Tiling: CTA = 64 rows x 64 gate-cols, K chunks of 64, 256 threads (8 warps,
// warp tile 16m x 32n). A (x,h) plain fp16; W resident hi+lo; pass1 f32-accum,
// pass2 (W-lo correction) f16-accum.
#define ROWB   144             // smem row stride (64 fp16 = 128B + 16B pad)
#define PLANE  (64 * ROWB)     // 9216 B per 64x64 fp16 plane
#define SK_CHUNKS 10           // 640/64
#define CLS_CHUNKS 8           // 512/64
#define NABUF  5               // A pipeline depth (chunk i -> buf i%5)
#define WREGION (SK_CHUNKS * 2 * PLANE)          // 184320 B resident W
#define PERS_SMEM (NABUF * PLANE + WREGION)      // 230400 B
#define CLS_STAGE (3 * PLANE)                    // A + Whi + Wlo
#define CLS_SMEM (2 * CLS_STAGE)                 // 55296 B

// ---------------------------------------------------------------------------
// Device scratch
// ---------------------------------------------------------------------------
__device__ __half g_Xh[(size_t)TT * BB * NIN];    // fp16 [x|dt]
__device__ __half g_Whi[(size_t)NGATE * KTOT];    // permuted: row 4j+g
__device__ __half g_Wlo[(size_t)NGATE * KTOT];
__device__ __half g_Wchi[(size_t)NOUT * NH];
__device__ __half g_Wclo[(size_t)NOUT * NH];
__device__ float  g_bias[NGATE];
__device__ __half g_Hh[(size_t)(TT + 1) * BB * NH];  // slot s = h_{s-1}
// barrier slots: one per (mg, nt) producer, 128 B apart (no atomic pileup).
// slot(mg,nt) holds the last step number that CTA has published.
__device__ unsigned g_slot[4 * 32 * 32];

// ---------------------------------------------------------------------------
// Helpers
// ---------------------------------------------------------------------------
__device__ __forceinline__ uint32_t smem_u32(const void* p) {
    uint32_t a;
    asm("{ .reg .u64 t; cvta.to.shared.u64 t, %1; cvt.u32.u64 %0, t; }" : "=r"(a) : "l"(p));
    return a;
}

__device__ __forceinline__ void ldsm4(uint32_t addr, uint32_t r[4]) {
    asm volatile("ldmatrix.sync.aligned.m8n8.x4.shared.b16 {%0,%1,%2,%3}, [%4];"
                 : "=r"(r[0]), "=r"(r[1]), "=r"(r[2]), "=r"(r[3]) : "r"(addr));
}

__device__ __forceinline__ void mma16816(float c[4], const uint32_t a[4],
                                         uint32_t b0, uint32_t b1) {
    asm volatile("mma.sync.aligned.m16n8k16.row.col.f32.f16.f16.f32 "
                 "{%0,%1,%2,%3}, {%4,%5,%6,%7}, {%8,%9}, {%0,%1,%2,%3};"
                 : "+f"(c[0]), "+f"(c[1]), "+f"(c[2]), "+f"(c[3])
                 : "r"(a[0]), "r"(a[1]), "r"(a[2]), "r"(a[3]), "r"(b0), "r"(b1));
}

// fp16-accumulator variant (2x HMMA rate) for the small W-lo correction.
__device__ __forceinline__ void mma16816_f16(uint32_t c[2], const uint32_t a[4],
                                             uint32_t b0, uint32_t b1) {
    asm volatile("mma.sync.aligned.m16n8k16.row.col.f16.f16.f16.f16 "
                 "{%0,%1}, {%2,%3,%4,%5}, {%6,%7}, {%0,%1};"
                 : "+r"(c[0]), "+r"(c[1])
                 : "r"(a[0]), "r"(a[1]), "r"(a[2]), "r"(a[3]), "r"(b0), "r"(b1));
}

__device__ __forceinline__ void cpa16(uint32_t dst, const void* src) {
    asm volatile("cp.async.cg.shared.global [%0], [%1], 16;" :: "r"(dst), "l"(src));
}
#define CP_COMMIT() asm volatile("cp.async.commit_group;" ::: "memory")

__device__ __forceinline__ float fsigmoid(float x) {
    x = fminf(fmaxf(x, -30.f), 30.f);
    return __fdividef(1.0f, 1.0f + __expf(-x));
}
__device__ __forceinline__ float ftanh(float x) {
    x = fminf(fmaxf(x, -15.f), 15.f);
    float e = __expf(-2.0f * x);
    return __fdividef(1.0f - e, 1.0f + e);
}

// Load one 64x64 fp16 plane via cp.async, 256 threads (one commit group).
__device__ __forceinline__ void load_A(uint32_t dst, int tid,
                                       const __half* src0, int astr) {
#pragma unroll
    for (int i = 0; i < 2; i++) {
        int idx = tid + 256 * i;               // 0..511
        int r = idx >> 3, ch = idx & 7;
        cpa16(dst + r * ROWB + ch * 16, src0 + (size_t)r * astr + ch * 8);
    }
    CP_COMMIT();
}

// One K=64 chunk, warp tile 16m x 32n:
// pass1 c += A*Whi (f32 accum), pass2 clo += A*Wlo (f16 accum).
__device__ __forceinline__ void compute_chunk(uint32_t abase, uint32_t wbase,
                                              int mwb, int nwb,
                                              uint32_t aoff, uint32_t boff,
                                              float c[4][4], uint32_t clo[4][2]) {
#pragma unroll
    for (int kk = 0; kk < 4; kk++) {
        uint32_t a[4], bhi[2][4], blo[2][4];
        ldsm4(abase + (uint32_t)mwb * ROWB + kk * 32 + aoff, a);
#pragma unroll
        for (int q = 0; q < 2; q++) {
            uint32_t base = wbase + (uint32_t)(nwb + q * 16) * ROWB + kk * 32 + boff;
            ldsm4(base, bhi[q]);
            ldsm4(base + PLANE, blo[q]);
        }
#pragma unroll
        for (int j = 0; j < 4; j++)
            mma16816(c[j], a, bhi[j >> 1][(j & 1) * 2], bhi[j >> 1][(j & 1) * 2 + 1]);
#pragma unroll
        for (int j = 0; j < 4; j++)
            mma16816_f16(clo[j], a, blo[j >> 1][(j & 1) * 2], blo[j >> 1][(j & 1) * 2 + 1]);
    }
}

__device__ __forceinline__ void zero_acc(float c[4][4], uint32_t clo[4][2]) {
#pragma unroll
    for (int b = 0; b < 4; b++) {
#pragma unroll
        for (int d = 0; d < 4; d++) c[b][d] = 0.f;
        clo[b][0] = 0u; clo[b][1] = 0u;
    }
}

__device__ __forceinline__ void merge_lo(float c[4][4], const uint32_t clo[4][2]) {
#pragma unroll
    for (int b = 0; b < 4; b++) {
        float2 f0 = __half22float2(*(const __half2*)&clo[b][0]);
        float2 f1 = __half22float2(*(const __half2*)&clo[b][1]);
        c[b][0] += f0.x; c[b][1] += f0.y;
        c[b][2] += f1.x; c[b][3] += f1.y;
    }
}

// ---------------------------------------------------------------------------
// Prep kernels
// ---------------------------------------------------------------------------
__device__ __forceinline__ void split16(float v, __half* hi, __half* lo) {
    __half h = __float2half_rn(v);
    *hi = h;
    *lo = __float2half_rn(v - __half2float(h));
}

__global__ void prep_w(const float* __restrict__ W_ih, const float* __restrict__ W_hh,
                       const float* __restrict__ b_ih, const float* __restrict__ b_hh) {
    int idx = blockIdx.x * 256 + threadIdx.x;
    if (idx < NGATE * KTOT) {
        int p = idx / KTOT, k = idx - p * KTOT;
        int j = p >> 2, g = p & 3;
        int srow = g * NH + j;
        float v = (k < NIN) ? W_ih[(size_t)srow * NIN + k]
                            : W_hh[(size_t)srow * NH + (k - NIN)];
        split16(v, &g_Whi[idx], &g_Wlo[idx]);
    }
    if (idx < NGATE) {
        int j = idx >> 2, g = idx & 3;
        g_bias[idx] = b_ih[g * NH + j] + b_hh[g * NH + j];
    }
}

__global__ void prep_wcls(const float* __restrict__ W_cls) {
    int idx = blockIdx.x * 256 + threadIdx.x;
    if (idx < NOUT * NH) split16(W_cls[idx], &g_Wchi[idx], &g_Wclo[idx]);
}

__global__ void prep_x(const float* __restrict__ input, const float* __restrict__ dtv) {
    int idx = blockIdx.x * 256 + threadIdx.x;
    if (idx < TT * BB * NIN) {
        int k = idx & (NIN - 1);
        int tb = idx >> 7;
        float v = (k < NIN - 1) ? input[(size_t)tb * (NIN - 1) + k] : dtv[tb];
        g_Xh[idx] = __float2half_rn(v);
    }
}

__global__ void prep_zero() {
    int idx = blockIdx.x * 256 + threadIdx.x;
    if (idx < 4 * 32 * 32) g_slot[idx] = 0;
    if (idx < BB * NH) g_Hh[idx] = __float2half_rn(0.0f);   // h_{-1}
}

// ---------------------------------------------------------------------------
// Persistent kernel: all 512 LSTM steps in one launch.
// grid (32 n-tiles, 4 m-groups) = 128 CTAs (1/SM), 256 threads (8 warps).
// W resident in smem; c in registers; paired-chunk loop (R15). R16 change:
// the per-mg barrier uses per-producer SLOTS (plain st.release to distinct
// 128B-apart lines — no same-address atomic serialization) and a 32-lane
// parallel acquire-poll (lane L watches producer L) + ballot. Monolithic
// barrier semantics, cheaper mechanics; arithmetic bit-identical to R15.
// ---------------------------------------------------------------------------
__global__ void __launch_bounds__(256) persistent_step() {
    extern __shared__ char dyn[];
    __shared__ float s_bias[64];

    const uint32_t sb = smem_u32(dyn);                 // 5 A buffers
    const uint32_t wb = sb + NABUF * PLANE;            // resident W region
    const int tid = threadIdx.x, L = tid & 31, wid = tid >> 5;
    const int nt = blockIdx.x, mg = blockIdx.y, mbase = mg * 64;

    if (tid < 64) s_bias[tid] = g_bias[nt * 64 + tid];

    // --- resident W: 10 chunks x (hi,lo) planes, one cp.async group ---
#pragma unroll 4
    for (int i = 0; i < 40; i++) {
        int idx = tid + 256 * i;                       // 0..10239
        int pl = idx >> 9;                             // plane 0..19
        int rem = idx & 511, r = rem >> 3, ch = rem & 7;
        int s = pl >> 1, hl = pl & 1;
        const __half* src = (hl ? g_Wlo : g_Whi)
                          + (size_t)(nt * 64 + r) * KTOT + s * 64 + ch * 8;
        cpa16(wb + (uint32_t)pl * PLANE + r * ROWB + ch * 16, src);
    }
    CP_COMMIT();

    const int mwb = (wid & 3) * 16, nwb = (wid >> 2) * 32;
    const uint32_t aoff = (uint32_t)((((L >> 3) & 1) * 8 + (L & 7)) * ROWB + (L >> 4) * 16);
    const uint32_t boff = (uint32_t)(((L >> 4) * 8 + (L & 7)) * ROWB + ((L >> 3) & 1) * 16);

    // W must be resident before t=0 chunk compute (x waits handled in-loop)
    asm volatile("cp.async.wait_group 0;" ::: "memory");
    __syncthreads();

    // --- x chunks 0,1 of t=0 into bufs 0,1 (waited at loop top) ---
    {
        const __half* xr = g_Xh + (size_t)mbase * NIN;
        load_A(sb,         tid, xr,      NIN);
        load_A(sb + PLANE, tid, xr + 64, NIN);
    }

    // bias for this thread's 4 (row,unit) cells: unit = nwb/4 + 2j + ((L&3)>>1)
    const int u0 = (L & 3) >> 1;
    float breg[4][4];
#pragma unroll
    for (int j = 0; j < 4; j++) {
        int ul = (nwb >> 2) + 2 * j + u0;
#pragma unroll
        for (int k = 0; k < 4; k++) breg[j][k] = s_bias[ul * 4 + k];
    }
    const int row_l = mwb + (L >> 2) + ((L & 1) << 3);
    float creg[4];
#pragma unroll
    for (int j = 0; j < 4; j++) creg[j] = 0.f;

    unsigned* my_slot = g_slot + ((size_t)(mg * 32 + nt)) * 32;
    const unsigned* poll_slot = g_slot + ((size_t)(mg * 32 + L)) * 32;  // lane L -> producer L
    char* stage = dyn + 2 * PLANE;     // epilogue staging (buf-2 region, quiescent)

    float c[4][4];
    uint32_t clo[4][2];

#pragma unroll 1
    for (int t = 0; t < TT; t++) {
        const __half* hrow = g_Hh + ((size_t)t * BB + mbase) * NH;

        // h chunks 2,3,4 -> bufs 2,3,4
        load_A(sb + 2 * PLANE, tid, hrow,       NH);
        load_A(sb + 3 * PLANE, tid, hrow + 64,  NH);
        load_A(sb + 4 * PLANE, tid, hrow + 128, NH);

        // retire x0,x1 (issued ~a full step ago: nearly free) + make visible
        asm volatile("cp.async.wait_group 3;" ::: "memory");
        __syncthreads();

        // chunks 0,1 (x) — overlaps h-load latency
        zero_acc(c, clo);
        compute_chunk(sb,         wb,             mwb, nwb, aoff, boff, c, clo);
        compute_chunk(sb + PLANE, wb + 2 * PLANE, mwb, nwb, aoff, boff, c, clo);

        // --- paired chunk loop: 4 sync points ---
#pragma unroll 1
        for (int i = 2; i < SK_CHUNKS; i += 2) {
            if (i <= 6) asm volatile("cp.async.wait_group 1;" ::: "memory");
            else        asm volatile("cp.async.wait_group 0;" ::: "memory");
            __syncthreads();   // chunks i,i+1 visible; bufs for i+3,i+4 free
            if (i <= 4) {      // issue loads for chunks i+3, i+4
                load_A(sb + (uint32_t)((i + 3) % 5) * PLANE, tid, hrow + (i + 1) * 64, NH);
                load_A(sb + (uint32_t)((i + 4) % 5) * PLANE, tid, hrow + (i + 2) * 64, NH);
            } else if (i == 6) {   // chunk 9 only
                load_A(sb + 4 * PLANE, tid, hrow + 7 * 64, NH);
            }
            compute_chunk(sb + (uint32_t)(i % 5) * PLANE,
                          wb + (uint32_t)i * 2 * PLANE,
                          mwb, nwb, aoff, boff, c, clo);
            compute_chunk(sb + (uint32_t)((i + 1) % 5) * PLANE,
                          wb + (uint32_t)(i + 1) * 2 * PLANE,
                          mwb, nwb, aoff, boff, c, clo);
        }

        // issue x(t+1) NOW — DRAM latency hides under epilogue + barrier.
        if (t + 1 < TT) {
            const __half* xr = g_Xh + ((size_t)(t + 1) * BB + mbase) * NIN;
            load_A(sb,         tid, xr,      NIN);
            load_A(sb + PLANE, tid, xr + 64, NIN);
        }

        merge_lo(c, clo);

        // --- shfl epilogue: lane-pair exchange (even: i,f | odd: g,o) ---
#pragma unroll
        for (int j = 0; j < 4; j++) {
            float s0 = __shfl_xor_sync(0xffffffffu, (L & 1) ? c[j][0] : c[j][2], 1);
            float s1 = __shfl_xor_sync(0xffffffffu, (L & 1) ? c[j][1] : c[j][3], 1);
            float iv, fv, gg, ov;
            if (!(L & 1)) { iv = c[j][0]; fv = c[j][1]; gg = s0;       ov = s1;       }
            else          { iv = s0;       fv = s1;       gg = c[j][2]; ov = c[j][3]; }
            iv = fsigmoid(iv + breg[j][0]);
            fv = fsigmoid(fv + breg[j][1]);
            gg = ftanh(gg + breg[j][2]);
            ov = fsigmoid(ov + breg[j][3]);
            float cv = fv * creg[j] + iv * gg;
            creg[j] = cv;
            int ul = (nwb >> 2) + 2 * j + u0;
            *(__half*)(stage + row_l * 32 + ul * 2) = __float2half_rn(ov * ftanh(cv));
        }
        __syncthreads();
        // coalesced h store: 64 rows x 16 units fp16
        {
            int row = tid >> 2, seg = tid & 3;
            uint2 v = *(uint2*)(stage + row * 32 + seg * 8);
            *(uint2*)(g_Hh + ((size_t)(t + 1) * BB + mbase + row) * NH + nt * 16 + seg * 4) = v;
        }
        __syncthreads();

        // publish step completion: plain release-store to OWN slot (no atomic)
        if (tid == 0)
            asm volatile("st.release.gpu.global.u32 [%0], %1;"
                         :: "l"(my_slot), "r"((unsigned)(t + 1)) : "memory");

        if (t + 1 < TT) {
            // barrier: warp 0 polls all 32 producer slots in parallel
            if (tid < 32) {
                const unsigned tgt = (unsigned)(t + 1);
                unsigned long long guard = 0;
                while (true) {
                    unsigned v;
                    asm volatile("ld.acquire.gpu.global.u32 %0, [%1];"
                                 : "=r"(v) : "l"(poll_slot));
                    if (__all_sync(0xffffffffu, (int)(v - tgt) >= 0)) break;
                    if (++guard > 200000000ULL) __trap();   // loud abort on deadlock
                }
            }
            __syncthreads();
        }
    }
}

// ---------------------------------------------------------------------------
// Classifier: out[131072,64] = hs @ W_cls^T + b_cls. grid 2048 x 256 thr.
// ---------------------------------------------------------------------------
__global__ void __launch_bounds__(256) cls_kernel(const float* __restrict__ b_cls,
                                                  float* __restrict__ out) {
    extern __shared__ char dyn[];
    __shared__ float s_bias[64];

    const uint32_t sb = smem_u32(dyn);
    const int tid = threadIdx.x, L = tid & 31, wid = tid >> 5;
    const size_t mb = (size_t)blockIdx.x * 64;

    if (tid < 64) s_bias[tid] = b_cls[tid];

    const __half* a0 = g_Hh + (BB + mb) * NH;   // hs rows (skip slot 0)

    load_A(sb,             tid, a0,     NH);
    load_A(sb + PLANE,     tid, g_Wchi, NH);
    load_A(sb + 2 * PLANE, tid, g_Wclo, NH);

    float c[4][4];
    uint32_t clo[4][2];
    zero_acc(c, clo);

    const int mwb = (wid & 3) * 16, nwb = (wid >> 2) * 32;
    const uint32_t aoff = (uint32_t)((((L >> 3) & 1) * 8 + (L & 7)) * ROWB + (L >> 4) * 16);
    const uint32_t boff = (uint32_t)(((L >> 4) * 8 + (L & 7)) * ROWB + ((L >> 3) & 1) * 16);

#pragma unroll 1
    for (int s = 0; s < CLS_CHUNKS; s++) {
        if (s + 1 < CLS_CHUNKS) {
            int sn = s + 1;
            uint32_t nb = sb + (sn & 1) * CLS_STAGE;
            load_A(nb,             tid, a0 + sn * 64,     NH);
            load_A(nb + PLANE,     tid, g_Wchi + sn * 64, NH);
            load_A(nb + 2 * PLANE, tid, g_Wclo + sn * 64, NH);
            asm volatile("cp.async.wait_group 3;" ::: "memory");
        } else {
            asm volatile("cp.async.wait_group 0;" ::: "memory");
        }
        __syncthreads();
        uint32_t base = sb + (s & 1) * CLS_STAGE;
        compute_chunk(base, base + PLANE, mwb, nwb, aoff, boff, c, clo);
        __syncthreads();
    }

    merge_lo(c, clo);

#pragma unroll
    for (int j = 0; j < 4; j++) {
        int row = mwb + (L >> 2);
        int col = nwb + j * 8 + 2 * (L & 3);
        float2 bb = *(const float2*)((const char*)s_bias + col * 4);
        float* op = out + (mb + row) * NOUT + col;
        *(float2*)op = make_float2(c[j][0] + bb.x, c[j][1] + bb.y);
        *(float2*)(op + 8 * NOUT) = make_float2(c[j][2] + bb.x, c[j][3] + bb.y);
    }
}

// ---------------------------------------------------------------------------
// Launch
// ---------------------------------------------------------------------------
extern "C" void kernel_launch(void* const* d_in, const int* in_sizes, int n_in,
                              void* d_out, int out_size) {
    const float* input = (const float*)d_in[0];
    const float* dtv   = (const float*)d_in[1];
    const float* W_ih  = (const float*)d_in[2];
    const float* W_hh  = (const float*)d_in[3];
    const float* b_ih  = (const float*)d_in[4];
    const float* b_hh  = (const float*)d_in[5];
    const float* W_cls = (const float*)d_in[6];
    const float* b_cls = (const float*)d_in[7];
    float* out = (float*)d_out;

    cudaFuncSetAttribute(persistent_step, cudaFuncAttributeMaxDynamicSharedMemorySize, PERS_SMEM);
    cudaFuncSetAttribute(cls_kernel, cudaFuncAttributeMaxDynamicSharedMemorySize, CLS_SMEM);

    prep_w<<<(NGATE * KTOT + 255) / 256, 256>>>(W_ih, W_hh, b_ih, b_hh);
    prep_wcls<<<(NOUT * NH + 255) / 256, 256>>>(W_cls);
    prep_x<<<(TT * BB * NIN + 255) / 256, 256>>>(input, dtv);
    prep_zero<<<(BB * NH + 255) / 256, 256>>>();

    persistent_step<<<dim3(32, 4), 256, PERS_SMEM>>>();
    cls_kernel<<<2048, 256, CLS_SMEM>>>(b_cls, out);
}

// round 17
// speedup vs baseline: 1.9258x; 1.9258x over previous
#include <cuda_runtime.h>
#include <cuda_fp16.h>
#include <cstdint>
#include <cstddef>

// ---------------------------------------------------------------------------
// Problem constants
// ---------------------------------------------------------------------------
#define TT    512
#define BB    256
#define NIN   128      // NINP (127 input + 1 dt)
#define NH    512      // NHID
#define NGATE 2048     // 4*NHID
#define KTOT  640      // NIN + NH
#define NOUT  64

// Tiling: CTA = 64 rows x 64 gate-cols, K chunks of 64, 256 threads (8 warps,
// warp tile 16m x 32n). A (x,h) plain fp16; W plain fp16 (single pass, f32
// accum) — W-lo correction dropped in the recurrence (kept in classifier).
#define ROWB   144             // smem row stride (64 fp16 = 128B + 16B pad)
#define PLANE  (64 * ROWB)     // 9216 B per 64x64 fp16 plane
#define SK_CHUNKS 10           // 640/64
#define CLS_CHUNKS 8           // 512/64
#define NABUF  5               // A pipeline depth (chunk i -> buf i%5)
#define WREGION (SK_CHUNKS * PLANE)              // 92160 B resident W (1 plane/chunk)
#define PERS_SMEM (NABUF * PLANE + WREGION)      // 138240 B
#define CLS_STAGE (3 * PLANE)                    // A + Whi + Wlo
#define CLS_SMEM (2 * CLS_STAGE)                 // 55296 B

// ---------------------------------------------------------------------------
// Device scratch
// ---------------------------------------------------------------------------
__device__ __half g_Xh[(size_t)TT * BB * NIN];    // fp16 [x|dt]
__device__ __half g_Wh[(size_t)NGATE * KTOT];     // permuted: row 4j+g (fp16)
__device__ __half g_Wchi[(size_t)NOUT * NH];      // classifier W hi/lo
__device__ __half g_Wclo[(size_t)NOUT * NH];
__device__ float  g_bias[NGATE];
__device__ __half g_Hh[(size_t)(TT + 1) * BB * NH];  // slot s = h_{s-1}
__device__ unsigned g_barA[128];                  // 4 per-mg counters (stride 32)

// ---------------------------------------------------------------------------
// Helpers
// ---------------------------------------------------------------------------
__device__ __forceinline__ uint32_t smem_u32(const void* p) {
    uint32_t a;
    asm("{ .reg .u64 t; cvta.to.shared.u64 t, %1; cvt.u32.u64 %0, t; }" : "=r"(a) : "l"(p));
    return a;
}

__device__ __forceinline__ void ldsm4(uint32_t addr, uint32_t r[4]) {
    asm volatile("ldmatrix.sync.aligned.m8n8.x4.shared.b16 {%0,%1,%2,%3}, [%4];"
                 : "=r"(r[0]), "=r"(r[1]), "=r"(r[2]), "=r"(r[3]) : "r"(addr));
}

__device__ __forceinline__ void mma16816(float c[4], const uint32_t a[4],
                                         uint32_t b0, uint32_t b1) {
    asm volatile("mma.sync.aligned.m16n8k16.row.col.f32.f16.f16.f32 "
                 "{%0,%1,%2,%3}, {%4,%5,%6,%7}, {%8,%9}, {%0,%1,%2,%3};"
                 : "+f"(c[0]), "+f"(c[1]), "+f"(c[2]), "+f"(c[3])
                 : "r"(a[0]), "r"(a[1]), "r"(a[2]), "r"(a[3]), "r"(b0), "r"(b1));
}

// fp16-accumulator variant (2x HMMA rate) for the classifier W-lo correction.
__device__ __forceinline__ void mma16816_f16(uint32_t c[2], const uint32_t a[4],
                                             uint32_t b0, uint32_t b1) {
    asm volatile("mma.sync.aligned.m16n8k16.row.col.f16.f16.f16.f16 "
                 "{%0,%1}, {%2,%3,%4,%5}, {%6,%7}, {%0,%1};"
                 : "+r"(c[0]), "+r"(c[1])
                 : "r"(a[0]), "r"(a[1]), "r"(a[2]), "r"(a[3]), "r"(b0), "r"(b1));
}

__device__ __forceinline__ void cpa16(uint32_t dst, const void* src) {
    asm volatile("cp.async.cg.shared.global [%0], [%1], 16;" :: "r"(dst), "l"(src));
}
#define CP_COMMIT() asm volatile("cp.async.commit_group;" ::: "memory")

__device__ __forceinline__ float fsigmoid(float x) {
    x = fminf(fmaxf(x, -30.f), 30.f);
    return __fdividef(1.0f, 1.0f + __expf(-x));
}
__device__ __forceinline__ float ftanh(float x) {
    x = fminf(fmaxf(x, -15.f), 15.f);
    float e = __expf(-2.0f * x);
    return __fdividef(1.0f - e, 1.0f + e);
}

// Load one 64x64 fp16 plane via cp.async, 256 threads (one commit group).
__device__ __forceinline__ void load_A(uint32_t dst, int tid,
                                       const __half* src0, int astr) {
#pragma unroll
    for (int i = 0; i < 2; i++) {
        int idx = tid + 256 * i;               // 0..511
        int r = idx >> 3, ch = idx & 7;
        cpa16(dst + r * ROWB + ch * 16, src0 + (size_t)r * astr + ch * 8);
    }
    CP_COMMIT();
}

// Step-kernel chunk: single pass c += A*W (f32 accum). Warp tile 16m x 32n.
__device__ __forceinline__ void compute_chunk1(uint32_t abase, uint32_t wbase,
                                               int mwb, int nwb,
                                               uint32_t aoff, uint32_t boff,
                                               float c[4][4]) {
#pragma unroll
    for (int kk = 0; kk < 4; kk++) {
        uint32_t a[4], bhi[2][4];
        ldsm4(abase + (uint32_t)mwb * ROWB + kk * 32 + aoff, a);
#pragma unroll
        for (int q = 0; q < 2; q++)
            ldsm4(wbase + (uint32_t)(nwb + q * 16) * ROWB + kk * 32 + boff, bhi[q]);
#pragma unroll
        for (int j = 0; j < 4; j++)
            mma16816(c[j], a, bhi[j >> 1][(j & 1) * 2], bhi[j >> 1][(j & 1) * 2 + 1]);
    }
}

// Classifier chunk: 2-pass hi/lo (unchanged numerics).
__device__ __forceinline__ void compute_chunk2(uint32_t abase, uint32_t wbase,
                                               int mwb, int nwb,
                                               uint32_t aoff, uint32_t boff,
                                               float c[4][4], uint32_t clo[4][2]) {
#pragma unroll
    for (int kk = 0; kk < 4; kk++) {
        uint32_t a[4], bhi[2][4], blo[2][4];
        ldsm4(abase + (uint32_t)mwb * ROWB + kk * 32 + aoff, a);
#pragma unroll
        for (int q = 0; q < 2; q++) {
            uint32_t base = wbase + (uint32_t)(nwb + q * 16) * ROWB + kk * 32 + boff;
            ldsm4(base, bhi[q]);
            ldsm4(base + PLANE, blo[q]);
        }
#pragma unroll
        for (int j = 0; j < 4; j++)
            mma16816(c[j], a, bhi[j >> 1][(j & 1) * 2], bhi[j >> 1][(j & 1) * 2 + 1]);
#pragma unroll
        for (int j = 0; j < 4; j++)
            mma16816_f16(clo[j], a, blo[j >> 1][(j & 1) * 2], blo[j >> 1][(j & 1) * 2 + 1]);
    }
}

__device__ __forceinline__ void merge_lo(float c[4][4], const uint32_t clo[4][2]) {
#pragma unroll
    for (int b = 0; b < 4; b++) {
        float2 f0 = __half22float2(*(const __half2*)&clo[b][0]);
        float2 f1 = __half22float2(*(const __half2*)&clo[b][1]);
        c[b][0] += f0.x; c[b][1] += f0.y;
        c[b][2] += f1.x; c[b][3] += f1.y;
    }
}

// ---------------------------------------------------------------------------
// Prep kernels
// ---------------------------------------------------------------------------
__device__ __forceinline__ void split16(float v, __half* hi, __half* lo) {
    __half h = __float2half_rn(v);
    *hi = h;
    *lo = __float2half_rn(v - __half2float(h));
}

__global__ void prep_w(const float* __restrict__ W_ih, const float* __restrict__ W_hh,
                       const float* __restrict__ b_ih, const float* __restrict__ b_hh) {
    int idx = blockIdx.x * 256 + threadIdx.x;
    if (idx < NGATE * KTOT) {
        int p = idx / KTOT, k = idx - p * KTOT;
        int j = p >> 2, g = p & 3;
        int srow = g * NH + j;
        float v = (k < NIN) ? W_ih[(size_t)srow * NIN + k]
                            : W_hh[(size_t)srow * NH + (k - NIN)];
        g_Wh[idx] = __float2half_rn(v);
    }
    if (idx < NGATE) {
        int j = idx >> 2, g = idx & 3;
        g_bias[idx] = b_ih[g * NH + j] + b_hh[g * NH + j];
    }
}

__global__ void prep_wcls(const float* __restrict__ W_cls) {
    int idx = blockIdx.x * 256 + threadIdx.x;
    if (idx < NOUT * NH) split16(W_cls[idx], &g_Wchi[idx], &g_Wclo[idx]);
}

__global__ void prep_x(const float* __restrict__ input, const float* __restrict__ dtv) {
    int idx = blockIdx.x * 256 + threadIdx.x;
    if (idx < TT * BB * NIN) {
        int k = idx & (NIN - 1);
        int tb = idx >> 7;
        float v = (k < NIN - 1) ? input[(size_t)tb * (NIN - 1) + k] : dtv[tb];
        g_Xh[idx] = __float2half_rn(v);
    }
}

__global__ void prep_zero() {
    int idx = blockIdx.x * 256 + threadIdx.x;
    if (idx < 128) g_barA[idx] = 0;
    if (idx < BB * NH) g_Hh[idx] = __float2half_rn(0.0f);   // h_{-1}
}

// ---------------------------------------------------------------------------
// Persistent kernel: all 512 LSTM steps in one launch.
// grid (32 n-tiles, 4 m-groups) = 128 CTAs (1/SM), 256 threads (8 warps).
// W (single fp16 plane per chunk) resident in smem; c in registers; per-mg
// monolithic barrier (R15 mechanics — three finer-grained designs falsified);
// paired-chunk loop (4 sync points). MMA work halved vs R15.
// ---------------------------------------------------------------------------
__global__ void __launch_bounds__(256) persistent_step() {
    extern __shared__ char dyn[];
    __shared__ float s_bias[64];

    const uint32_t sb = smem_u32(dyn);                 // 5 A buffers
    const uint32_t wb = sb + NABUF * PLANE;            // resident W region
    const int tid = threadIdx.x, L = tid & 31, wid = tid >> 5;
    const int nt = blockIdx.x, mg = blockIdx.y, mbase = mg * 64;

    if (tid < 64) s_bias[tid] = g_bias[nt * 64 + tid];

    // --- resident W: 10 chunk planes (10 commit groups, retired below) ---
#pragma unroll
    for (int s = 0; s < SK_CHUNKS; s++)
        load_A(wb + (uint32_t)s * PLANE, tid,
               g_Wh + (size_t)(nt * 64) * KTOT + s * 64, KTOT);

    const int mwb = (wid & 3) * 16, nwb = (wid >> 2) * 32;
    const uint32_t aoff = (uint32_t)((((L >> 3) & 1) * 8 + (L & 7)) * ROWB + (L >> 4) * 16);
    const uint32_t boff = (uint32_t)(((L >> 4) * 8 + (L & 7)) * ROWB + ((L >> 3) & 1) * 16);

    // W must be resident before t=0 chunk compute (x waits handled in-loop)
    asm volatile("cp.async.wait_group 0;" ::: "memory");
    __syncthreads();

    // --- x chunks 0,1 of t=0 into bufs 0,1 (waited at loop top) ---
    {
        const __half* xr = g_Xh + (size_t)mbase * NIN;
        load_A(sb,         tid, xr,      NIN);
        load_A(sb + PLANE, tid, xr + 64, NIN);
    }

    // bias for this thread's 4 (row,unit) cells: unit = nwb/4 + 2j + ((L&3)>>1)
    const int u0 = (L & 3) >> 1;
    float breg[4][4];
#pragma unroll
    for (int j = 0; j < 4; j++) {
        int ul = (nwb >> 2) + 2 * j + u0;
#pragma unroll
        for (int k = 0; k < 4; k++) breg[j][k] = s_bias[ul * 4 + k];
    }
    const int row_l = mwb + (L >> 2) + ((L & 1) << 3);
    float creg[4];
#pragma unroll
    for (int j = 0; j < 4; j++) creg[j] = 0.f;

    unsigned* barp = &g_barA[mg * 32];
    char* stage = dyn + 2 * PLANE;     // epilogue staging (buf-2 region, quiescent)

    float c[4][4];

#pragma unroll 1
    for (int t = 0; t < TT; t++) {
        const __half* hrow = g_Hh + ((size_t)t * BB + mbase) * NH;

        // h chunks 2,3,4 -> bufs 2,3,4
        load_A(sb + 2 * PLANE, tid, hrow,       NH);
        load_A(sb + 3 * PLANE, tid, hrow + 64,  NH);
        load_A(sb + 4 * PLANE, tid, hrow + 128, NH);

        // retire x0,x1 (issued ~a full step ago: nearly free) + make visible
        asm volatile("cp.async.wait_group 3;" ::: "memory");
        __syncthreads();

        // chunks 0,1 (x) — overlaps h-load latency
#pragma unroll
        for (int b = 0; b < 4; b++)
#pragma unroll
            for (int d = 0; d < 4; d++) c[b][d] = 0.f;
        compute_chunk1(sb,         wb,         mwb, nwb, aoff, boff, c);
        compute_chunk1(sb + PLANE, wb + PLANE, mwb, nwb, aoff, boff, c);

        // --- paired chunk loop: 4 sync points ---
#pragma unroll 1
        for (int i = 2; i < SK_CHUNKS; i += 2) {
            if (i <= 6) asm volatile("cp.async.wait_group 1;" ::: "memory");
            else        asm volatile("cp.async.wait_group 0;" ::: "memory");
            __syncthreads();   // chunks i,i+1 visible; bufs for i+3,i+4 free
            if (i <= 4) {      // issue loads for chunks i+3, i+4
                load_A(sb + (uint32_t)((i + 3) % 5) * PLANE, tid, hrow + (i + 1) * 64, NH);
                load_A(sb + (uint32_t)((i + 4) % 5) * PLANE, tid, hrow + (i + 2) * 64, NH);
            } else if (i == 6) {   // chunk 9 only
                load_A(sb + 4 * PLANE, tid, hrow + 7 * 64, NH);
            }
            compute_chunk1(sb + (uint32_t)(i % 5) * PLANE,
                           wb + (uint32_t)i * PLANE,
                           mwb, nwb, aoff, boff, c);
            compute_chunk1(sb + (uint32_t)((i + 1) % 5) * PLANE,
                           wb + (uint32_t)(i + 1) * PLANE,
                           mwb, nwb, aoff, boff, c);
        }

        // issue x(t+1) NOW — DRAM latency hides under epilogue + barrier.
        if (t + 1 < TT) {
            const __half* xr = g_Xh + ((size_t)(t + 1) * BB + mbase) * NIN;
            load_A(sb,         tid, xr,      NIN);
            load_A(sb + PLANE, tid, xr + 64, NIN);
        }

        // --- shfl epilogue: lane-pair exchange (even: i,f | odd: g,o) ---
#pragma unroll
        for (int j = 0; j < 4; j++) {
            float s0 = __shfl_xor_sync(0xffffffffu, (L & 1) ? c[j][0] : c[j][2], 1);
            float s1 = __shfl_xor_sync(0xffffffffu, (L & 1) ? c[j][1] : c[j][3], 1);
            float iv, fv, gg, ov;
            if (!(L & 1)) { iv = c[j][0]; fv = c[j][1]; gg = s0;       ov = s1;       }
            else          { iv = s0;       fv = s1;       gg = c[j][2]; ov = c[j][3]; }
            iv = fsigmoid(iv + breg[j][0]);
            fv = fsigmoid(fv + breg[j][1]);
            gg = ftanh(gg + breg[j][2]);
            ov = fsigmoid(ov + breg[j][3]);
            float cv = fv * creg[j] + iv * gg;
            creg[j] = cv;
            int ul = (nwb >> 2) + 2 * j + u0;
            *(__half*)(stage + row_l * 32 + ul * 2) = __float2half_rn(ov * ftanh(cv));
        }
        __syncthreads();
        // coalesced h store: 64 rows x 16 units fp16
        {
            int row = tid >> 2, seg = tid & 3;
            uint2 v = *(uint2*)(stage + row * 32 + seg * 8);
            *(uint2*)(g_Hh + ((size_t)(t + 1) * BB + mbase + row) * NH + nt * 16 + seg * 4) = v;
        }
        __syncthreads();

        // arrive with release semantics (orders the h stores)
        if (tid == 0)
            asm volatile("red.release.gpu.global.add.u32 [%0], %1;"
                         :: "l"(barp), "r"(1u) : "memory");

        if (t + 1 < TT) {
            // per-mg barrier: h_t rows of this m-group visible to its 32 CTAs
            if (tid == 0) {
                const unsigned target = 32u * (unsigned)(t + 1);
                unsigned v;
                unsigned long long guard = 0;
                do {
                    asm volatile("ld.acquire.gpu.global.u32 %0, [%1];" : "=r"(v) : "l"(barp));
                    if (v >= target) break;
                    if (++guard > 400000000ULL) __trap();   // loud abort on deadlock
                } while (true);
            }
            __syncthreads();
        }
    }
}

// ---------------------------------------------------------------------------
// Classifier: out[131072,64] = hs @ W_cls^T + b_cls. grid 2048 x 256 thr.
// Keeps the 2-pass hi/lo W path (one-shot kernel, unchanged numerics).
// ---------------------------------------------------------------------------
__global__ void __launch_bounds__(256) cls_kernel(const float* __restrict__ b_cls,
                                                  float* __restrict__ out) {
    extern __shared__ char dyn[];
    __shared__ float s_bias[64];

    const uint32_t sb = smem_u32(dyn);
    const int tid = threadIdx.x, L = tid & 31, wid = tid >> 5;
    const size_t mb = (size_t)blockIdx.x * 64;

    if (tid < 64) s_bias[tid] = b_cls[tid];

    const __half* a0 = g_Hh + (BB + mb) * NH;   // hs rows (skip slot 0)

    load_A(sb,             tid, a0,     NH);
    load_A(sb + PLANE,     tid, g_Wchi, NH);
    load_A(sb + 2 * PLANE, tid, g_Wclo, NH);

    float c[4][4];
    uint32_t clo[4][2];
#pragma unroll
    for (int b = 0; b < 4; b++) {
#pragma unroll
        for (int d = 0; d < 4; d++) c[b][d] = 0.f;
        clo[b][0] = 0u; clo[b][1] = 0u;
    }

    const int mwb = (wid & 3) * 16, nwb = (wid >> 2) * 32;
    const uint32_t aoff = (uint32_t)((((L >> 3) & 1) * 8 + (L & 7)) * ROWB + (L >> 4) * 16);
    const uint32_t boff = (uint32_t)(((L >> 4) * 8 + (L & 7)) * ROWB + ((L >> 3) & 1) * 16);

#pragma unroll 1
    for (int s = 0; s < CLS_CHUNKS; s++) {
        if (s + 1 < CLS_CHUNKS) {
            int sn = s + 1;
            uint32_t nb = sb + (sn & 1) * CLS_STAGE;
            load_A(nb,             tid, a0 + sn * 64,     NH);
            load_A(nb + PLANE,     tid, g_Wchi + sn * 64, NH);
            load_A(nb + 2 * PLANE, tid, g_Wclo + sn * 64, NH);
            asm volatile("cp.async.wait_group 3;" ::: "memory");
        } else {
            asm volatile("cp.async.wait_group 0;" ::: "memory");
        }
        __syncthreads();
        uint32_t base = sb + (s & 1) * CLS_STAGE;
        compute_chunk2(base, base + PLANE, mwb, nwb, aoff, boff, c, clo);
        __syncthreads();
    }

    merge_lo(c, clo);

#pragma unroll
    for (int j = 0; j < 4; j++) {
        int row = mwb + (L >> 2);
        int col = nwb + j * 8 + 2 * (L & 3);
        float2 bb = *(const float2*)((const char*)s_bias + col * 4);
        float* op = out + (mb + row) * NOUT + col;
        *(float2*)op = make_float2(c[j][0] + bb.x, c[j][1] + bb.y);
        *(float2*)(op + 8 * NOUT) = make_float2(c[j][2] + bb.x, c[j][3] + bb.y);
    }
}

// ---------------------------------------------------------------------------
// Launch
// ---------------------------------------------------------------------------
extern "C" void kernel_launch(void* const* d_in, const int* in_sizes, int n_in,
                              void* d_out, int out_size) {
    const float* input = (const float*)d_in[0];
    const float* dtv   = (const float*)d_in[1];
    const float* W_ih  = (const float*)d_in[2];
    const float* W_hh  = (const float*)d_in[3];
    const float* b_ih  = (const float*)d_in[4];
    const float* b_hh  = (const float*)d_in[5];
    const float* W_cls = (const float*)d_in[6];
    const float* b_cls = (const float*)d_in[7];
    float* out = (float*)d_out;

    cudaFuncSetAttribute(persistent_step, cudaFuncAttributeMaxDynamicSharedMemorySize, PERS_SMEM);
    cudaFuncSetAttribute(cls_kernel, cudaFuncAttributeMaxDynamicSharedMemorySize, CLS_SMEM);

    prep_w<<<(NGATE * KTOT + 255) / 256, 256>>>(W_ih, W_hh, b_ih, b_hh);
    prep_wcls<<<(NOUT * NH + 255) / 256, 256>>>(W_cls);
    prep_x<<<(TT * BB * NIN + 255) / 256, 256>>>(input, dtv);
    prep_zero<<<(BB * NH + 255) / 256, 256>>>();

    persistent_step<<<dim3(32, 4), 256, PERS_SMEM>>>();
    cls_kernel<<<2048, 256, CLS_SMEM>>>(b_cls, out);
}